// round 1
// baseline (speedup 1.0000x reference)
#include <cuda_runtime.h>
#include <cstdint>

// Upscaler: W=8, R=4. out[b,t,h] = wa*Z[b,t>>2,h] + wb*Z[b,(t>>2)-1,h]
// wa = 0.25*(t&3), wb = 1 - wa. Row-normalization denom == 1.0f in fp32 for i0>=1.
// For i0==0 (t<4): out = Z[b,0,h] * wa/(wa+1e-8f).

static constexpr int B_ = 4;
static constexpr int N_ = 2048;
static constexpr int H_ = 1024;
static constexpr int S_ = 8192;
static constexpr int H4 = H_ / 4;   // 256 float4 per row

__global__ __launch_bounds__(H4, 8)
void Upscaler_33294586479031_kernel(const float4* __restrict__ Z,
                                    float4* __restrict__ out)
{
    const int t = blockIdx.x;      // 0..S-1
    const int b = blockIdx.y;      // 0..B-1
    const int h = threadIdx.x;     // 0..H4-1

    const int i0 = t >> 2;
    const int r  = t & 3;
    const float wa = 0.25f * (float)r;
    const float wb = 1.0f - wa;

    const float4* za_ptr = Z + ((size_t)b * N_ + i0) * H4 + h;
    float4 a = *za_ptr;
    float4 res;

    if (i0 == 0) {
        // only block 0 valid: normalize by (wa + eps)
        const float s = wa / (wa + 1e-8f);   // 0 for r==0
        res.x = a.x * s; res.y = a.y * s; res.z = a.z * s; res.w = a.w * s;
    } else {
        float4 c = *(za_ptr - H4);           // Z[b, i0-1, h]
        res.x = fmaf(wa, a.x, wb * c.x);
        res.y = fmaf(wa, a.y, wb * c.y);
        res.z = fmaf(wa, a.z, wb * c.z);
        res.w = fmaf(wa, a.w, wb * c.w);
    }

    out[((size_t)b * S_ + t) * H4 + h] = res;
}

extern "C" void kernel_launch(void* const* d_in, const int* in_sizes, int n_in,
                              void* d_out, int out_size)
{
    const float4* Z = (const float4*)d_in[0];
    float4* out = (float4*)d_out;

    dim3 grid(S_, B_);
    dim3 block(H4);
    Upscaler_33294586479031_kernel<<<grid, block>>>(Z, out);
}

// round 2
// speedup vs baseline: 1.3150x; 1.3150x over previous
#include <cuda_runtime.h>
#include <cstdint>

// Upscaler W=8, R=4: out[b, 4*i0+r, h] = (0.25r)*Z[b,i0,h] + (1-0.25r)*Z[b,i0-1,h]
// (row-norm denominator == 1.0f in fp32 for i0>=1; i0==0 handled specially).
// One CTA per (i0, b): load two Z rows once, emit 4 output rows.

static constexpr int B_ = 4;
static constexpr int N_ = 2048;
static constexpr int H_ = 1024;
static constexpr int S_ = 8192;
static constexpr int H4 = H_ / 4;   // 256 float4 lanes per row

__global__ __launch_bounds__(H4, 8)
void Upscaler_33294586479031_kernel(const float4* __restrict__ Z,
                                    float4* __restrict__ out)
{
    const int i0 = blockIdx.x;     // 0..N-1
    const int b  = blockIdx.y;     // 0..B-1
    const int h  = threadIdx.x;    // 0..H4-1

    const float4* za_ptr = Z + ((size_t)b * N_ + i0) * H4 + h;
    // Two independent loads, batched up front (MLP=2).
    const float4 a = *za_ptr;                         // Z[b, i0,   h]
    float4 c;
    if (i0 > 0) c = *(za_ptr - H4);                   // Z[b, i0-1, h]

    float4* o = out + ((size_t)b * S_ + 4 * (size_t)i0) * H4 + h;

    if (i0 > 0) {
        #pragma unroll
        for (int r = 0; r < 4; ++r) {
            const float wa = 0.25f * (float)r;
            const float wb = 1.0f - wa;
            float4 res;
            res.x = fmaf(wa, a.x, wb * c.x);
            res.y = fmaf(wa, a.y, wb * c.y);
            res.z = fmaf(wa, a.z, wb * c.z);
            res.w = fmaf(wa, a.w, wb * c.w);
            o[(size_t)r * H4] = res;
        }
    } else {
        // i0 == 0: only block 0 overlaps; normalize by (wa + eps).
        #pragma unroll
        for (int r = 0; r < 4; ++r) {
            const float wa = 0.25f * (float)r;
            const float s  = wa / (wa + 1e-8f);       // 0 when r==0
            float4 res;
            res.x = a.x * s; res.y = a.y * s; res.z = a.z * s; res.w = a.w * s;
            o[(size_t)r * H4] = res;
        }
    }
}

extern "C" void kernel_launch(void* const* d_in, const int* in_sizes, int n_in,
                              void* d_out, int out_size)
{
    const float4* Z = (const float4*)d_in[0];
    float4* out = (float4*)d_out;

    dim3 grid(N_, B_);
    dim3 block(H4);
    Upscaler_33294586479031_kernel<<<grid, block>>>(Z, out);
}

// round 3
// speedup vs baseline: 1.4330x; 1.0897x over previous
#include <cuda_runtime.h>
#include <cstdint>

// Upscaler W=8, R=4: out[b, 4*i+r, h] = (0.25r)*Z[b,i,h] + (1-0.25r)*Z[b,i-1,h]
// Row-norm denominator == 1.0f exactly in fp32 for i>=1; i==0 normalized by (wa+eps).
// One CTA per (i0 pair, b): 3 batched loads, 8 streaming stores per thread.

static constexpr int B_ = 4;
static constexpr int N_ = 2048;
static constexpr int H_ = 1024;
static constexpr int S_ = 8192;
static constexpr int H4 = H_ / 4;   // 256 float4 lanes per row

__device__ __forceinline__ float4 blend(float wa, float wb, float4 a, float4 c) {
    float4 r;
    r.x = fmaf(wa, a.x, wb * c.x);
    r.y = fmaf(wa, a.y, wb * c.y);
    r.z = fmaf(wa, a.z, wb * c.z);
    r.w = fmaf(wa, a.w, wb * c.w);
    return r;
}

__global__ __launch_bounds__(H4, 8)
void Upscaler_33294586479031_kernel(const float4* __restrict__ Z,
                                    float4* __restrict__ out)
{
    const int i0 = blockIdx.x * 2;   // even block index, 0..N-2
    const int b  = blockIdx.y;       // 0..B-1
    const int h  = threadIdx.x;      // 0..H4-1

    const float4* zp = Z + ((size_t)b * N_ + i0) * H4 + h;

    // Front-batched independent loads (MLP = 3)
    const float4 z0 = zp[0];                 // Z[b, i0,   h]
    const float4 z1 = zp[H4];                // Z[b, i0+1, h]
    float4 zm;
    if (i0 > 0) zm = zp[-H4];                // Z[b, i0-1, h]

    float4* o = out + ((size_t)b * S_ + 4 * (size_t)i0) * H4 + h;

    // Rows 4..7: blocks (i0, i0+1) — never the edge case.
    #pragma unroll
    for (int r = 0; r < 4; ++r) {
        const float wa = 0.25f * (float)r;
        __stcs(&o[(size_t)(r + 4) * H4], blend(wa, 1.0f - wa, z1, z0));
    }

    // Rows 0..3: blocks (i0-1, i0).
    if (i0 > 0) {
        #pragma unroll
        for (int r = 0; r < 4; ++r) {
            const float wa = 0.25f * (float)r;
            __stcs(&o[(size_t)r * H4], blend(wa, 1.0f - wa, z0, zm));
        }
    } else {
        #pragma unroll
        for (int r = 0; r < 4; ++r) {
            const float wa = 0.25f * (float)r;
            const float s  = wa / (wa + 1e-8f);     // 0 when r==0
            float4 res;
            res.x = z0.x * s; res.y = z0.y * s; res.z = z0.z * s; res.w = z0.w * s;
            __stcs(&o[(size_t)r * H4], res);
        }
    }
}

extern "C" void kernel_launch(void* const* d_in, const int* in_sizes, int n_in,
                              void* d_out, int out_size)
{
    const float4* Z = (const float4*)d_in[0];
    float4* out = (float4*)d_out;

    dim3 grid(N_ / 2, B_);
    dim3 block(H4);
    Upscaler_33294586479031_kernel<<<grid, block>>>(Z, out);
}